// round 12
// baseline (speedup 1.0000x reference)
#include <cuda_runtime.h>
#include <cuda_bf16.h>

// ROI bilinear pooling (TF2 half_pixel_centers resize semantics).
// img: [1, 100, 100, 512] f32 NHWC ; rois: [1, 300, 4] int32 (x, y, w, h)
// out: [1, 300, 14, 14, 512] f32
//
// R11 (= R9 resubmit; two prior runs were broker-level infra failures):
// maximize warp-level parallelism with a lean body. 256-thread blocks, one
// block per (roi, py); thread t owns float2 chunk t of the 512-channel row
// (256 chunks). Per px: 4x LDG.64 + 8 FFMA + 1 STG.64. launch_bounds(256,8)
// => 2048 thr/SM = 64 warps = 100% theoretical occupancy (regs auto-capped
// at 32). Coord precompute in smem (threads 0..13, one barrier). Loop not
// unrolled to keep regs under the cap: latency hiding comes from 64 warps
// instead of per-warp load batching.

#define POOL 14
#define NUM_ROIS 300
#define FM_H 100
#define FM_W 100
#define FM_C 512
#define C2 (FM_C / 2)            // 256 float2 per pixel row
#define NUM_ITEMS (NUM_ROIS * POOL)   // 4200

__global__ __launch_bounds__(256, 8)
void roi_pool_kernel(const float2* __restrict__ img2,
                     const int*    __restrict__ rois,
                     float2*       __restrict__ out2)
{
    __shared__ int4   s_off[POOL];   // float2-element offsets of the 4 gather rows
    __shared__ float4 s_w[POOL];     // bilinear weights w00,w01,w10,w11

    const int t    = threadIdx.x;    // 0..255 : one float2 chunk
    const int item = blockIdx.x;     // 0..4199 = (roi, py)

    if (t < POOL) {
        const int px = t;
        const int r  = item / POOL;
        const int py = item - r * POOL;

        const int4 roi = __ldg(((const int4*)rois) + r);
        const int rx = roi.x, ry = roi.y, rw = roi.z, rh = roi.w;

        // y axis (half-pixel centers)
        const float srcy = (py + 0.5f) * ((float)rh * (1.0f / POOL)) - 0.5f;
        const float fy   = floorf(srcy);
        const float ty   = srcy - fy;
        const int   fyi  = (int)fy;
        const int   ylo  = min(max(fyi,     0), rh - 1) + ry;
        const int   yhi  = min(max(fyi + 1, 0), rh - 1) + ry;

        // x axis
        const float srcx = (px + 0.5f) * ((float)rw * (1.0f / POOL)) - 0.5f;
        const float fx   = floorf(srcx);
        const float tx   = srcx - fx;
        const int   fxi  = (int)fx;
        const int   xlo  = min(max(fxi,     0), rw - 1) + rx;
        const int   xhi  = min(max(fxi + 1, 0), rw - 1) + rx;

        const int rowlo = ylo * (FM_W * C2);   // float2 index of row start
        const int rowhi = yhi * (FM_W * C2);

        int4 off;
        off.x = rowlo + xlo * C2;   // (ylo, xlo)
        off.y = rowlo + xhi * C2;   // (ylo, xhi)
        off.z = rowhi + xlo * C2;   // (yhi, xlo)
        off.w = rowhi + xhi * C2;   // (yhi, xhi)
        s_off[px] = off;

        const float wy0 = 1.0f - ty, wy1 = ty;
        const float wx0 = 1.0f - tx, wx1 = tx;
        float4 w;
        w.x = wy0 * wx0;
        w.y = wy0 * wx1;
        w.z = wy1 * wx0;
        w.w = wy1 * wx1;
        s_w[px] = w;
    }
    __syncthreads();

    float2* optr = out2 + (size_t)item * (POOL * C2) + t;

    #pragma unroll 1
    for (int px = 0; px < POOL; ++px) {
        const int4   off = s_off[px];   // broadcast LDS.128
        const float4 w   = s_w[px];     // broadcast LDS.128

        const float2 a  = __ldg(img2 + off.x + t);
        const float2 bq = __ldg(img2 + off.y + t);
        const float2 c  = __ldg(img2 + off.z + t);
        const float2 d  = __ldg(img2 + off.w + t);

        float2 o;
        o.x = w.x * a.x + w.y * bq.x + w.z * c.x + w.w * d.x;
        o.y = w.x * a.y + w.y * bq.y + w.z * c.y + w.w * d.y;

        __stcs(optr + px * C2, o);   // streaming store: output never re-read
    }
}

extern "C" void kernel_launch(void* const* d_in, const int* in_sizes, int n_in,
                              void* d_out, int out_size)
{
    // Resolve inputs by size, not position: img = 5,120,000 elems; rois = 1,200.
    const float* img;
    const int*   rois;
    if (in_sizes[0] > in_sizes[1]) {
        img  = (const float*)d_in[0];
        rois = (const int*)d_in[1];
    } else {
        img  = (const float*)d_in[1];
        rois = (const int*)d_in[0];
    }
    float* out = (float*)d_out;

    roi_pool_kernel<<<NUM_ITEMS, 256>>>((const float2*)img, rois, (float2*)out);
}